// round 15
// baseline (speedup 1.0000x reference)
#include <cuda_runtime.h>
#include <math.h>

#define NB     32
#define NA     33600
#define K_TOP  1000
#define NBINS  2048      // coarse bins: score_bits >> 19
#define NSUB   2048      // refine bins: bits[18:8]
#define NCAND  2048
#define NA4    (NA / 4)  // 8400
#define NCHUNK 33        // ceil(NA4 / 256) score chunks per batch
#define NDET   (NB * K_TOP)

// scratch (static device globals — no allocation).
// g_hist is zero-initialized at module load; decode_kernel re-zeroes it at the
// end of EVERY call, so each kernel_launch invocation sees a zeroed histogram
// (deterministic, identical work per call, graph-safe).
__device__ float        g_scores[NB * NA];        // 4.3 MB, L2-resident
__device__ int          g_keep[NDET];             // anchor per (batch, rank)
__device__ unsigned int g_hist[NB * NBINS];       // per-batch coarse histograms

// Bitwise match of XLA GPU logistic: 1/(1+exp(-x)) with libdevice expf and
// IEEE div.rn (nvcc defaults, no fast-math). DO NOT refactor algebraically —
// output ordering must be bit-exact vs reference (rel_err 5e-9 confirms).
__device__ __forceinline__ float sigref(float x) {
    return 1.0f / (1.0f + expf(-x));
}

// ---------------------------------------------------------------------------
// Kernel 1: score[b,a] = sigmoid(cls)*sigmoid(obj), float4-vectorized,
// batch-aligned CTAs + smem-private histogram flushed to g_hist (sparse).
// ---------------------------------------------------------------------------
__global__ __launch_bounds__(256) void score_kernel(
        const float* __restrict__ cls0, const float* __restrict__ cls1,
        const float* __restrict__ cls2,
        const float* __restrict__ obj0, const float* __restrict__ obj1,
        const float* __restrict__ obj2) {
    __shared__ unsigned int h[NBINS];
    int b     = blockIdx.x / NCHUNK;
    int chunk = blockIdx.x - b * NCHUNK;
    int tid   = threadIdx.x;

    for (int q = tid; q < NBINS; q += 256) h[q] = 0u;
    __syncthreads();

    int a4 = chunk * 256 + tid;
    if (a4 < NA4) {
        const float4 *cp, *op;
        int p4;
        if (a4 < 6400)      { cp = (const float4*)cls0 + b * 6400; op = (const float4*)obj0 + b * 6400; p4 = a4; }
        else if (a4 < 8000) { cp = (const float4*)cls1 + b * 1600; op = (const float4*)obj1 + b * 1600; p4 = a4 - 6400; }
        else                { cp = (const float4*)cls2 + b * 400;  op = (const float4*)obj2 + b * 400;  p4 = a4 - 8000; }
        float4 c = cp[p4];
        float4 o = op[p4];
        float4 r;
        r.x = sigref(c.x) * sigref(o.x);
        r.y = sigref(c.y) * sigref(o.y);
        r.z = sigref(c.z) * sigref(o.z);
        r.w = sigref(c.w) * sigref(o.w);
        ((float4*)g_scores)[b * NA4 + a4] = r;
        atomicAdd(&h[__float_as_uint(r.x) >> 19], 1u);
        atomicAdd(&h[__float_as_uint(r.y) >> 19], 1u);
        atomicAdd(&h[__float_as_uint(r.z) >> 19], 1u);
        atomicAdd(&h[__float_as_uint(r.w) >> 19], 1u);
    }
    __syncthreads();

    // Sparse flush: only active bins (~100-300 per CTA), spread addresses.
    unsigned int* gh = g_hist + b * NBINS;
    for (int q = tid; q < NBINS; q += 256) {
        unsigned int cnum = h[q];
        if (cnum) atomicAdd(&gh[q], cnum);
    }
}

// ---------------------------------------------------------------------------
// Kernel 2: exact sorted top-1000 per batch (one CTA per batch, 1024 threads)
// Histogram comes precomputed from score_kernel: only ONE data pass here.
// ---------------------------------------------------------------------------
__device__ void find_thresh(const unsigned int* hist, int nbins, int K, int tid,
                            int* wsum, int* s_bin, int* s_above) {
    int per  = nbins >> 10;
    int base = nbins - 1 - tid * per;
    int tsum = 0;
    for (int q = 0; q < per; q++) tsum += (int)hist[base - q];

    int lane = tid & 31, wid = tid >> 5;
    int x = tsum;
#pragma unroll
    for (int d = 1; d < 32; d <<= 1) {
        int n = __shfl_up_sync(0xffffffffu, x, d);
        if (lane >= d) x += n;
    }
    if (lane == 31) wsum[wid] = x;
    __syncthreads();
    if (wid == 0) {
        int w = wsum[lane];
#pragma unroll
        for (int d = 1; d < 32; d <<= 1) {
            int n = __shfl_up_sync(0xffffffffu, w, d);
            if (lane >= d) w += n;
        }
        wsum[lane] = w;
    }
    __syncthreads();
    int excl = (wid == 0 ? 0 : wsum[wid - 1]) + (x - tsum);

    if (excl < K && excl + tsum >= K) {     // exactly one thread
        int c = excl;
        for (int q = 0; q < per; q++) {
            int bin = base - q;
            int h = (int)hist[bin];
            if (c + h >= K) { *s_bin = bin; *s_above = c; break; }
            c += h;
        }
    }
    __syncthreads();
}

__global__ __launch_bounds__(1024) void topk_kernel(float* __restrict__ dout) {
    __shared__ unsigned int       hist[NBINS];    // 8 KB: coarse hist (from g_hist)
    __shared__ unsigned int       scanv[NBINS];   // 8 KB: refine hist -> cbase -> group end
    __shared__ unsigned long long cand[NCAND];    // 16 KB: bin-grouped candidates
    __shared__ int  wsum[32];
    __shared__ int  s_bin, s_above;
    __shared__ unsigned int s_total;

    int b = blockIdx.x;
    int tid = threadIdx.x;
    const uint4* sv = (const uint4*)(g_scores + b * NA);

    // Phase 1: coarse histogram comes from score_kernel (L2 read, no data pass).
    for (int q = tid; q < NBINS; q += 1024) hist[q] = g_hist[b * NBINS + q];
    __syncthreads();
    find_thresh(hist, NBINS, K_TOP, tid, wsum, &s_bin, &s_above);
    int T = s_bin;
    int need2 = K_TOP - s_above;
    int binT_count = (int)hist[T];
    __syncthreads();

    unsigned int cut;
    int keptT;
    if (s_above + binT_count <= NCAND) {
        cut = (unsigned int)T << 19;        // keep all of bin T
        keptT = binT_count;
    } else {
        // Rare: refine bin T on bits[18:8] (uses scanv as the sub-histogram).
        for (int q = tid; q < NSUB; q += 1024) scanv[q] = 0u;
        __syncthreads();
        for (int q = tid; q < NA4; q += 1024) {
            uint4 v = sv[q];
            if ((int)(v.x >> 19) == T) atomicAdd(&scanv[(v.x >> 8) & 2047u], 1u);
            if ((int)(v.y >> 19) == T) atomicAdd(&scanv[(v.y >> 8) & 2047u], 1u);
            if ((int)(v.z >> 19) == T) atomicAdd(&scanv[(v.z >> 8) & 2047u], 1u);
            if ((int)(v.w >> 19) == T) atomicAdd(&scanv[(v.w >> 8) & 2047u], 1u);
        }
        __syncthreads();
        find_thresh(scanv, NSUB, need2, tid, wsum, &s_bin, &s_above);
        cut = ((unsigned int)T << 19) | ((unsigned int)s_bin << 8);
        keptT = s_above + (int)scanv[s_bin];   // kept members of bin T
        __syncthreads();
    }

    // Phase 2: descending suffix scan of masked hist -> scanv[bin] = cbase.
    // val(bin) = hist[bin] for bin > T, keptT at T, 0 below.
    {
        int hi = NBINS - 1 - 2 * tid;
        unsigned int h1 = (hi > T) ? hist[hi] : (hi == T ? (unsigned int)keptT : 0u);
        int lo = hi - 1;
        unsigned int h0 = (lo > T) ? hist[lo] : (lo == T ? (unsigned int)keptT : 0u);
        int tsum = (int)(h1 + h0);
        int lane = tid & 31, wid = tid >> 5;
        int x = tsum;
#pragma unroll
        for (int d = 1; d < 32; d <<= 1) {
            int n = __shfl_up_sync(0xffffffffu, x, d);
            if (lane >= d) x += n;
        }
        if (lane == 31) wsum[wid] = x;
        __syncthreads();
        if (wid == 0) {
            int w = wsum[lane];
#pragma unroll
            for (int d = 1; d < 32; d <<= 1) {
                int n = __shfl_up_sync(0xffffffffu, w, d);
                if (lane >= d) w += n;
            }
            wsum[lane] = w;
        }
        __syncthreads();
        int excl = (wid == 0 ? 0 : wsum[wid - 1]) + (x - tsum);
        scanv[hi] = (unsigned int)excl;
        scanv[lo] = (unsigned int)excl + h1;
        if (lo == 0) s_total = (unsigned int)(excl + tsum);
    }
    __syncthreads();

    // Phase 3: place candidates grouped by bin (the ONE data pass over L2).
    // scanv[bin] is the cursor; after this phase scanv[bin] = group END.
    // key = (bits << 32) | ~index : bigger key == better (score desc, idx asc).
    for (int q = tid; q < NA4; q += 1024) {
        uint4 v = sv[q];
        int a0 = q * 4;
#pragma unroll
        for (int e = 0; e < 4; e++) {
            unsigned int bits = (e == 0) ? v.x : (e == 1) ? v.y : (e == 2) ? v.z : v.w;
            if (bits >= cut) {
                unsigned int bin = bits >> 19;
                unsigned int slot = atomicAdd(&scanv[bin], 1u);
                if (slot < NCAND)
                    cand[slot] = ((unsigned long long)bits << 32) |
                                 (unsigned long long)(0xFFFFFFFFu - (unsigned int)(a0 + e));
            }
        }
    }
    __syncthreads();
    int cnt = (int)s_total; if (cnt > NCAND) cnt = NCAND;

    // Phase 4: exact rank = group_start + #same-group candidates with larger key.
#pragma unroll
    for (int s0 = 0; s0 < 2; s0++) {
        int s = tid + s0 * 1024;
        if (s < cnt) {
            unsigned long long key = cand[s];
            unsigned int bin  = (unsigned int)(key >> 51);   // bits<2^30 -> bin<2048
            unsigned int endr = scanv[bin];
            unsigned int size = ((int)bin == T) ? (unsigned int)keptT : hist[bin];
            unsigned int start = endr - size;
            unsigned int end   = endr; if (end > (unsigned int)cnt) end = (unsigned int)cnt;
            int r = (int)start;
            for (unsigned int g = start; g < end; g++)
                r += (cand[g] > key);
            if (r < K_TOP) {
                unsigned int bits = (unsigned int)(key >> 32);
                unsigned int a    = 0xFFFFFFFFu - (unsigned int)(key & 0xFFFFFFFFull);
                g_keep[b * K_TOP + r] = (int)a;
                dout[b * (K_TOP * 5) + r * 5 + 4] = __uint_as_float(bits);
            }
        }
    }
}

// ---------------------------------------------------------------------------
// Kernel 3: decode kept anchors (18 tasks/det, det fast index) + re-zero
// g_hist for the next invocation (no extra launch).
// ---------------------------------------------------------------------------
__global__ void decode_kernel(const float* __restrict__ bbox0, const float* __restrict__ bbox1,
                              const float* __restrict__ bbox2,
                              const float* __restrict__ kpt0,  const float* __restrict__ kpt1,
                              const float* __restrict__ kpt2,
                              const float* __restrict__ vis0,  const float* __restrict__ vis1,
                              const float* __restrict__ vis2,
                              float* __restrict__ dout) {
    const int NTASK = NDET * 18;
    int task = blockIdx.x * blockDim.x + threadIdx.x;

    // Re-zero the histogram for the next call (topk already consumed it).
    if (task < NB * NBINS) g_hist[task] = 0u;

    if (task >= NTASK) return;
    int det = task % NDET;
    int sub = task / NDET;
    int b   = det / K_TOP;
    int a   = g_keep[det];

    int p, HW, l;
    float s, px, py;
    if (a < 25600)      { p = a;         HW = 25600; s = 8.0f;  l = 0; px = (float)(p % 160) * 8.0f;  py = (float)(p / 160) * 8.0f;  }
    else if (a < 32000) { p = a - 25600; HW = 6400;  s = 16.0f; l = 1; px = (float)(p % 80)  * 16.0f; py = (float)(p / 80)  * 16.0f; }
    else                { p = a - 32000; HW = 1600;  s = 32.0f; l = 2; px = (float)(p % 40)  * 32.0f; py = (float)(p / 40)  * 32.0f; }

    if (sub < 17) {
        int k = sub;
        const float* kp = (l == 0) ? kpt0 : (l == 1) ? kpt1 : kpt2;
        const float* vp = (l == 0) ? vis0 : (l == 1) ? vis1 : vis2;
        float kx = kp[(b * 34 + 2 * k)     * HW + p];
        float ky = kp[(b * 34 + 2 * k + 1) * HW + p];
        float v  = vp[(b * 17 + k)         * HW + p];
        int off = NDET * 5 + det * 51 + k * 3;
        dout[off + 0] = kx * s + px;
        dout[off + 1] = ky * s + py;
        dout[off + 2] = sigref(v);
    } else {
        const float* bp = (l == 0) ? bbox0 : (l == 1) ? bbox1 : bbox2;
        float bx = bp[(b * 4 + 0) * HW + p];
        float by = bp[(b * 4 + 1) * HW + p];
        float bw = bp[(b * 4 + 2) * HW + p];
        float bh = bp[(b * 4 + 3) * HW + p];
        float x  = bx * s + px;
        float y  = by * s + py;
        float hw = expf(bw) * s * 0.5f;
        float hh = expf(bh) * s * 0.5f;
        int off = det * 5;
        dout[off + 0] = x - hw;
        dout[off + 1] = y - hh;
        dout[off + 2] = x + hw;
        dout[off + 3] = y + hh;
    }
}

// ---------------------------------------------------------------------------
extern "C" void kernel_launch(void* const* d_in, const int* in_sizes, int n_in,
                              void* d_out, int out_size) {
    const float* cls0  = (const float*)d_in[0];
    const float* cls1  = (const float*)d_in[1];
    const float* cls2  = (const float*)d_in[2];
    const float* bbox0 = (const float*)d_in[3];
    const float* bbox1 = (const float*)d_in[4];
    const float* bbox2 = (const float*)d_in[5];
    const float* obj0  = (const float*)d_in[6];
    const float* obj1  = (const float*)d_in[7];
    const float* obj2  = (const float*)d_in[8];
    const float* kpt0  = (const float*)d_in[9];
    const float* kpt1  = (const float*)d_in[10];
    const float* kpt2  = (const float*)d_in[11];
    const float* vis0  = (const float*)d_in[12];
    const float* vis1  = (const float*)d_in[13];
    const float* vis2  = (const float*)d_in[14];
    float* dout = (float*)d_out;

    score_kernel<<<NB * NCHUNK, 256>>>(cls0, cls1, cls2, obj0, obj1, obj2);
    topk_kernel<<<NB, 1024>>>(dout);
    decode_kernel<<<(NDET * 18 + 255) / 256, 256>>>(bbox0, bbox1, bbox2,
                                                    kpt0, kpt1, kpt2,
                                                    vis0, vis1, vis2, dout);
}

// round 17
// speedup vs baseline: 1.1643x; 1.1643x over previous
#include <cuda_runtime.h>
#include <math.h>

#define NB     32
#define NA     33600
#define K_TOP  1000
#define NBINS  2048      // coarse bins: score_bits >> 19
#define NSUB   2048      // refine bins: bits[18:8]
#define NCAND  2048
#define NA4    (NA / 4)  // 8400
#define NDET   (NB * K_TOP)
#define DPB    32        // dets per decode CTA (32*51 = 1632 ≡ 0 mod 4 -> f4-aligned)

// scratch (static device globals — no allocation)
__device__ float g_scores[NB * NA];   // 4.3 MB, L2-resident
__device__ int   g_keep[NDET];        // anchor per (batch, rank)

// Bitwise match of XLA GPU logistic: 1/(1+exp(-x)) with libdevice expf and
// IEEE div.rn (nvcc defaults, no fast-math). DO NOT refactor algebraically —
// output ordering must be bit-exact vs reference (rel_err 5e-9 confirms).
__device__ __forceinline__ float sigref(float x) {
    return 1.0f / (1.0f + expf(-x));
}

// ---------------------------------------------------------------------------
// Kernel 1: score[b,a] = sigmoid(cls)*sigmoid(obj), float4-vectorized.
// (R13 exact — measured ~6.4us)
// ---------------------------------------------------------------------------
__global__ void score_kernel(const float* __restrict__ cls0, const float* __restrict__ cls1,
                             const float* __restrict__ cls2,
                             const float* __restrict__ obj0, const float* __restrict__ obj1,
                             const float* __restrict__ obj2) {
    int i4 = blockIdx.x * blockDim.x + threadIdx.x;
    if (i4 >= NB * NA4) return;
    int b  = i4 / NA4;
    int a4 = i4 - b * NA4;
    const float4 *cp, *op;
    int p4;
    if (a4 < 6400)      { cp = (const float4*)cls0 + b * 6400; op = (const float4*)obj0 + b * 6400; p4 = a4; }
    else if (a4 < 8000) { cp = (const float4*)cls1 + b * 1600; op = (const float4*)obj1 + b * 1600; p4 = a4 - 6400; }
    else                { cp = (const float4*)cls2 + b * 400;  op = (const float4*)obj2 + b * 400;  p4 = a4 - 8000; }
    float4 c = cp[p4];
    float4 o = op[p4];
    float4 r;
    r.x = sigref(c.x) * sigref(o.x);
    r.y = sigref(c.y) * sigref(o.y);
    r.z = sigref(c.z) * sigref(o.z);
    r.w = sigref(c.w) * sigref(o.w);
    ((float4*)g_scores)[i4] = r;
}

// ---------------------------------------------------------------------------
// Kernel 2: exact sorted top-1000 per batch (R13 exact — measured WIN).
// ---------------------------------------------------------------------------
__device__ void find_thresh(const unsigned int* hist, int nbins, int K, int tid,
                            int* wsum, int* s_bin, int* s_above) {
    int per  = nbins >> 10;
    int base = nbins - 1 - tid * per;
    int tsum = 0;
    for (int q = 0; q < per; q++) tsum += (int)hist[base - q];

    int lane = tid & 31, wid = tid >> 5;
    int x = tsum;
#pragma unroll
    for (int d = 1; d < 32; d <<= 1) {
        int n = __shfl_up_sync(0xffffffffu, x, d);
        if (lane >= d) x += n;
    }
    if (lane == 31) wsum[wid] = x;
    __syncthreads();
    if (wid == 0) {
        int w = wsum[lane];
#pragma unroll
        for (int d = 1; d < 32; d <<= 1) {
            int n = __shfl_up_sync(0xffffffffu, w, d);
            if (lane >= d) w += n;
        }
        wsum[lane] = w;
    }
    __syncthreads();
    int excl = (wid == 0 ? 0 : wsum[wid - 1]) + (x - tsum);

    if (excl < K && excl + tsum >= K) {     // exactly one thread
        int c = excl;
        for (int q = 0; q < per; q++) {
            int bin = base - q;
            int h = (int)hist[bin];
            if (c + h >= K) { *s_bin = bin; *s_above = c; break; }
            c += h;
        }
    }
    __syncthreads();
}

__global__ __launch_bounds__(1024) void topk_kernel(float* __restrict__ dout) {
    __shared__ unsigned int       hist[NBINS];    // 8 KB: coarse hist (preserved)
    __shared__ unsigned int       scanv[NBINS];   // 8 KB: refine hist -> cbase -> group end
    __shared__ unsigned long long cand[NCAND];    // 16 KB: bin-grouped candidates
    __shared__ int  wsum[32];
    __shared__ int  s_bin, s_above;
    __shared__ unsigned int s_total;

    int b = blockIdx.x;
    int tid = threadIdx.x;
    const uint4* sv = (const uint4*)(g_scores + b * NA);

    // Phase 1: coarse histogram on bits >> 19 (pass 1 over L2-resident scores).
    for (int q = tid; q < NBINS; q += 1024) hist[q] = 0u;
    __syncthreads();
    for (int q = tid; q < NA4; q += 1024) {
        uint4 v = sv[q];
        atomicAdd(&hist[v.x >> 19], 1u);
        atomicAdd(&hist[v.y >> 19], 1u);
        atomicAdd(&hist[v.z >> 19], 1u);
        atomicAdd(&hist[v.w >> 19], 1u);
    }
    __syncthreads();
    find_thresh(hist, NBINS, K_TOP, tid, wsum, &s_bin, &s_above);
    int T = s_bin;
    int need2 = K_TOP - s_above;
    int binT_count = (int)hist[T];
    __syncthreads();

    unsigned int cut;
    int keptT;
    if (s_above + binT_count <= NCAND) {
        cut = (unsigned int)T << 19;        // keep all of bin T
        keptT = binT_count;
    } else {
        // Rare: refine bin T on bits[18:8] (uses scanv as the sub-histogram).
        for (int q = tid; q < NSUB; q += 1024) scanv[q] = 0u;
        __syncthreads();
        for (int q = tid; q < NA4; q += 1024) {
            uint4 v = sv[q];
            if ((int)(v.x >> 19) == T) atomicAdd(&scanv[(v.x >> 8) & 2047u], 1u);
            if ((int)(v.y >> 19) == T) atomicAdd(&scanv[(v.y >> 8) & 2047u], 1u);
            if ((int)(v.z >> 19) == T) atomicAdd(&scanv[(v.z >> 8) & 2047u], 1u);
            if ((int)(v.w >> 19) == T) atomicAdd(&scanv[(v.w >> 8) & 2047u], 1u);
        }
        __syncthreads();
        find_thresh(scanv, NSUB, need2, tid, wsum, &s_bin, &s_above);
        cut = ((unsigned int)T << 19) | ((unsigned int)s_bin << 8);
        keptT = s_above + (int)scanv[s_bin];   // kept members of bin T
        __syncthreads();
    }

    // Phase 2: descending suffix scan of masked hist -> scanv[bin] = cbase.
    {
        int hi = NBINS - 1 - 2 * tid;
        unsigned int h1 = (hi > T) ? hist[hi] : (hi == T ? (unsigned int)keptT : 0u);
        int lo = hi - 1;
        unsigned int h0 = (lo > T) ? hist[lo] : (lo == T ? (unsigned int)keptT : 0u);
        int tsum = (int)(h1 + h0);
        int lane = tid & 31, wid = tid >> 5;
        int x = tsum;
#pragma unroll
        for (int d = 1; d < 32; d <<= 1) {
            int n = __shfl_up_sync(0xffffffffu, x, d);
            if (lane >= d) x += n;
        }
        if (lane == 31) wsum[wid] = x;
        __syncthreads();
        if (wid == 0) {
            int w = wsum[lane];
#pragma unroll
            for (int d = 1; d < 32; d <<= 1) {
                int n = __shfl_up_sync(0xffffffffu, w, d);
                if (lane >= d) w += n;
            }
            wsum[lane] = w;
        }
        __syncthreads();
        int excl = (wid == 0 ? 0 : wsum[wid - 1]) + (x - tsum);
        scanv[hi] = (unsigned int)excl;
        scanv[lo] = (unsigned int)excl + h1;
        if (lo == 0) s_total = (unsigned int)(excl + tsum);
    }
    __syncthreads();

    // Phase 3: place candidates grouped by bin (pass 2 over L2).
    for (int q = tid; q < NA4; q += 1024) {
        uint4 v = sv[q];
        int a0 = q * 4;
#pragma unroll
        for (int e = 0; e < 4; e++) {
            unsigned int bits = (e == 0) ? v.x : (e == 1) ? v.y : (e == 2) ? v.z : v.w;
            if (bits >= cut) {
                unsigned int bin = bits >> 19;
                unsigned int slot = atomicAdd(&scanv[bin], 1u);
                if (slot < NCAND)
                    cand[slot] = ((unsigned long long)bits << 32) |
                                 (unsigned long long)(0xFFFFFFFFu - (unsigned int)(a0 + e));
            }
        }
    }
    __syncthreads();
    int cnt = (int)s_total; if (cnt > NCAND) cnt = NCAND;

    // Phase 4: exact rank = group_start + #same-group candidates with larger key.
#pragma unroll
    for (int s0 = 0; s0 < 2; s0++) {
        int s = tid + s0 * 1024;
        if (s < cnt) {
            unsigned long long key = cand[s];
            unsigned int bin  = (unsigned int)(key >> 51);
            unsigned int endr = scanv[bin];
            unsigned int size = ((int)bin == T) ? (unsigned int)keptT : hist[bin];
            unsigned int start = endr - size;
            unsigned int end   = endr; if (end > (unsigned int)cnt) end = (unsigned int)cnt;
            int r = (int)start;
            for (unsigned int g = start; g < end; g++)
                r += (cand[g] > key);
            if (r < K_TOP) {
                unsigned int bits = (unsigned int)(key >> 32);
                unsigned int a    = 0xFFFFFFFFu - (unsigned int)(key & 0xFFFFFFFFull);
                g_keep[b * K_TOP + r] = (int)a;
                dout[b * (K_TOP * 5) + r * 5 + 4] = __uint_as_float(bits);
            }
        }
    }
}

// ---------------------------------------------------------------------------
// Kernel 3: decode with smem-staged, vectorized keypoint stores.
// CTA (256 thr) owns DPB=32 consecutive dets: compute 32x18 tasks into smem,
// then flush the 32x51-float kpt block as coalesced STG.128. Bbox columns
// (0..3) stay scalar because topk's score column (4) interleaves them.
// ---------------------------------------------------------------------------
__global__ __launch_bounds__(256) void decode_kernel(
        const float* __restrict__ bbox0, const float* __restrict__ bbox1,
        const float* __restrict__ bbox2,
        const float* __restrict__ kpt0,  const float* __restrict__ kpt1,
        const float* __restrict__ kpt2,
        const float* __restrict__ vis0,  const float* __restrict__ vis1,
        const float* __restrict__ vis2,
        float* __restrict__ dout) {
    __shared__ __align__(16) float skpt[DPB * 51];   // 6528 B staging
    int det0 = blockIdx.x * DPB;
    int tid  = threadIdx.x;

    // Compute phase: 32 dets x 18 subs. Lane = det offset (warp-uniform sub).
    for (int t = tid; t < DPB * 18; t += 256) {
        int d   = t & (DPB - 1);       // det offset within CTA (lane-fast)
        int sub = t >> 5;              // 0..16 kpt, 17 bbox (uniform per warp)
        int det = det0 + d;
        int b   = det / K_TOP;
        int a   = g_keep[det];

        int p, HW, l;
        float s, px, py;
        if (a < 25600)      { p = a;         HW = 25600; s = 8.0f;  l = 0; px = (float)(p % 160) * 8.0f;  py = (float)(p / 160) * 8.0f;  }
        else if (a < 32000) { p = a - 25600; HW = 6400;  s = 16.0f; l = 1; px = (float)(p % 80)  * 16.0f; py = (float)(p / 80)  * 16.0f; }
        else                { p = a - 32000; HW = 1600;  s = 32.0f; l = 2; px = (float)(p % 40)  * 32.0f; py = (float)(p / 40)  * 32.0f; }

        if (sub < 17) {
            int k = sub;
            const float* kp = (l == 0) ? kpt0 : (l == 1) ? kpt1 : kpt2;
            const float* vp = (l == 0) ? vis0 : (l == 1) ? vis1 : vis2;
            float kx = kp[(b * 34 + 2 * k)     * HW + p];
            float ky = kp[(b * 34 + 2 * k + 1) * HW + p];
            float v  = vp[(b * 17 + k)         * HW + p];
            int so = d * 51 + k * 3;
            skpt[so + 0] = kx * s + px;
            skpt[so + 1] = ky * s + py;
            skpt[so + 2] = sigref(v);
        } else {
            const float* bp = (l == 0) ? bbox0 : (l == 1) ? bbox1 : bbox2;
            float bx = bp[(b * 4 + 0) * HW + p];
            float by = bp[(b * 4 + 1) * HW + p];
            float bw = bp[(b * 4 + 2) * HW + p];
            float bh = bp[(b * 4 + 3) * HW + p];
            float x  = bx * s + px;
            float y  = by * s + py;
            float hw = expf(bw) * s * 0.5f;
            float hh = expf(bh) * s * 0.5f;
            int off = det * 5;
            dout[off + 0] = x - hw;
            dout[off + 1] = y - hh;
            dout[off + 2] = x + hw;
            dout[off + 3] = y + hh;
        }
    }
    __syncthreads();

    // Flush phase: DPB*51 = 1632 floats = 408 float4, base is f4-aligned
    // (NDET*5 = 160000 ≡ 0 mod 4 and det0*51 = blockIdx*1632 ≡ 0 mod 4).
    float4* dst = (float4*)(dout + NDET * 5 + det0 * 51);
    const float4* src = (const float4*)skpt;
#pragma unroll
    for (int i = tid; i < DPB * 51 / 4; i += 256)
        dst[i] = src[i];
}

// ---------------------------------------------------------------------------
extern "C" void kernel_launch(void* const* d_in, const int* in_sizes, int n_in,
                              void* d_out, int out_size) {
    const float* cls0  = (const float*)d_in[0];
    const float* cls1  = (const float*)d_in[1];
    const float* cls2  = (const float*)d_in[2];
    const float* bbox0 = (const float*)d_in[3];
    const float* bbox1 = (const float*)d_in[4];
    const float* bbox2 = (const float*)d_in[5];
    const float* obj0  = (const float*)d_in[6];
    const float* obj1  = (const float*)d_in[7];
    const float* obj2  = (const float*)d_in[8];
    const float* kpt0  = (const float*)d_in[9];
    const float* kpt1  = (const float*)d_in[10];
    const float* kpt2  = (const float*)d_in[11];
    const float* vis0  = (const float*)d_in[12];
    const float* vis1  = (const float*)d_in[13];
    const float* vis2  = (const float*)d_in[14];
    float* dout = (float*)d_out;

    score_kernel<<<(NB * NA4 + 255) / 256, 256>>>(cls0, cls1, cls2, obj0, obj1, obj2);
    topk_kernel<<<NB, 1024>>>(dout);
    decode_kernel<<<NDET / DPB, 256>>>(bbox0, bbox1, bbox2,
                                       kpt0, kpt1, kpt2,
                                       vis0, vis1, vis2, dout);
}